// round 1
// baseline (speedup 1.0000x reference)
#include <cuda_runtime.h>
#include <math_constants.h>

#define D 1024
#define NKEYS 32768
#define TOPK 10

// Scratch (allocation-free rule: __device__ globals)
__device__ float g_q[D];
__device__ float g_scores[NKEYS];
__device__ unsigned int g_max_enc;

// Order-preserving float->uint encoding (for atomicMax over signed floats)
__device__ __forceinline__ unsigned int fenc(float f) {
    unsigned int b = __float_as_uint(f);
    return (b & 0x80000000u) ? ~b : (b | 0x80000000u);
}
__device__ __forceinline__ float fdec(unsigned int u) {
    unsigned int b = (u & 0x80000000u) ? (u & 0x7FFFFFFFu) : ~u;
    return __uint_as_float(b);
}

// Kernel 1: q = Wq @ query + bq   (warp per output row)
__global__ void proj_kernel(const float* __restrict__ query,
                            const float* __restrict__ Wq,
                            const float* __restrict__ bq) {
    __shared__ float sq[D];
    int tid = threadIdx.x;
    for (int i = tid; i < D; i += 256) sq[i] = query[i];
    if (blockIdx.x == 0 && tid == 0) g_max_enc = 0u;  // reset for this launch
    __syncthreads();

    int warp = tid >> 5, lane = tid & 31;
    int row = blockIdx.x * 8 + warp;
    const float4* wrow = (const float4*)(Wq + (size_t)row * D);
    const float4* q4   = (const float4*)sq;

    float acc = 0.f;
    #pragma unroll
    for (int it = 0; it < 8; it++) {
        float4 w = wrow[lane + it * 32];
        float4 q = q4[lane + it * 32];
        acc += w.x * q.x + w.y * q.y + w.z * q.z + w.w * q.w;
    }
    #pragma unroll
    for (int o = 16; o; o >>= 1) acc += __shfl_xor_sync(0xFFFFFFFFu, acc, o);
    if (lane == 0) g_q[row] = acc + bq[row];
}

// Kernel 2: scores[i] = keys[i] . q  (warp per row) + global max via atomics
__global__ void gemv_kernel(const float* __restrict__ keys) {
    __shared__ float sq[D];
    __shared__ float srow[8];
    int tid = threadIdx.x;
    for (int i = tid; i < D; i += 256) sq[i] = g_q[i];
    __syncthreads();

    int warp = tid >> 5, lane = tid & 31;
    int row = blockIdx.x * 8 + warp;
    const float4* kr = (const float4*)(keys + (size_t)row * D);
    const float4* q4 = (const float4*)sq;

    float acc = 0.f;
    #pragma unroll
    for (int it = 0; it < 8; it++) {
        float4 kv = __ldg(&kr[lane + it * 32]);
        float4 q  = q4[lane + it * 32];
        acc += kv.x * q.x + kv.y * q.y + kv.z * q.z + kv.w * q.w;
    }
    #pragma unroll
    for (int o = 16; o; o >>= 1) acc += __shfl_xor_sync(0xFFFFFFFFu, acc, o);

    if (lane == 0) { g_scores[row] = acc; srow[warp] = acc; }
    __syncthreads();
    if (tid == 0) {
        float m = srow[0];
        #pragma unroll
        for (int i = 1; i < 8; i++) m = fmaxf(m, srow[i]);
        atomicMax(&g_max_enc, fenc(m));
    }
}

// Kernel 3 (single block, 256 threads): softmax denom + top-k + gather
__global__ void final_kernel(const float* __restrict__ values,
                             float* __restrict__ out) {
    __shared__ float sv[256 * TOPK];
    __shared__ int   si[256 * TOPK];
    __shared__ float s_red[8];
    __shared__ float s_sum;

    int tid = threadIdx.x;
    const float inv = 0.03125f;  // 1/sqrt(1024)
    float mx  = fdec(g_max_enc);
    float mxs = mx * inv;

    float lv[TOPK]; int li[TOPK];
    #pragma unroll
    for (int i = 0; i < TOPK; i++) { lv[i] = -CUDART_INF_F; li[i] = 0x7FFFFFFF; }

    float sum = 0.f;
    for (int i = tid; i < NKEYS; i += 256) {
        float s = g_scores[i];
        sum += expf(s * inv - mxs);
        if (s > lv[TOPK - 1]) {
            int j = TOPK - 1;
            while (j > 0 && s > lv[j - 1]) {  // strict: ties keep lower index first
                lv[j] = lv[j - 1]; li[j] = li[j - 1]; j--;
            }
            lv[j] = s; li[j] = i;
        }
    }

    // sum reduction
    #pragma unroll
    for (int o = 16; o; o >>= 1) sum += __shfl_xor_sync(0xFFFFFFFFu, sum, o);
    if ((tid & 31) == 0) s_red[tid >> 5] = sum;

    // publish local sorted lists
    #pragma unroll
    for (int i = 0; i < TOPK; i++) { sv[tid * TOPK + i] = lv[i]; si[tid * TOPK + i] = li[i]; }
    __syncthreads();

    if (tid == 0) {
        float t = 0.f;
        #pragma unroll
        for (int i = 0; i < 8; i++) t += s_red[i];
        s_sum = t;
    }

    // tree-merge 256 sorted 10-lists -> list at slot 0
    for (int step = 128; step >= 1; step >>= 1) {
        if (tid < step) {
            float av[TOPK], bv[TOPK], ov[TOPK];
            int   ai[TOPK], bi[TOPK], oi[TOPK];
            #pragma unroll
            for (int i = 0; i < TOPK; i++) {
                av[i] = sv[tid * TOPK + i];          ai[i] = si[tid * TOPK + i];
                bv[i] = sv[(tid + step) * TOPK + i]; bi[i] = si[(tid + step) * TOPK + i];
            }
            int pa = 0, pb = 0;
            #pragma unroll
            for (int r = 0; r < TOPK; r++) {
                // pa+pb == r < TOPK, so pa,pb <= TOPK-1 here: no OOB
                bool ta = (av[pa] > bv[pb]) || (av[pa] == bv[pb] && ai[pa] <= bi[pb]);
                if (ta) { ov[r] = av[pa]; oi[r] = ai[pa]; pa++; }
                else    { ov[r] = bv[pb]; oi[r] = bi[pb]; pb++; }
            }
            #pragma unroll
            for (int i = 0; i < TOPK; i++) { sv[tid * TOPK + i] = ov[i]; si[tid * TOPK + i] = oi[i]; }
        }
        __syncthreads();
    }

    // weights for top-k (descending order already)
    float total = s_sum;
    if (tid < TOPK) {
        float w = expf(sv[tid] * inv - mxs) / total;
        out[TOPK * D + tid] = w;
    }
    // gather value rows
    for (int r = 0; r < TOPK; r++) {
        int idx = si[r];
        const float* vr = values + (size_t)idx * D;
        for (int c = tid; c < D; c += 256) out[r * D + c] = vr[c];
    }
}

extern "C" void kernel_launch(void* const* d_in, const int* in_sizes, int n_in,
                              void* d_out, int out_size) {
    const float* query  = (const float*)d_in[0];
    const float* keys   = (const float*)d_in[1];
    const float* values = (const float*)d_in[2];
    const float* Wq     = (const float*)d_in[3];
    const float* bq     = (const float*)d_in[4];
    float* out = (float*)d_out;

    proj_kernel<<<D / 8, 256>>>(query, Wq, bq);
    gemv_kernel<<<NKEYS / 8, 256>>>(keys);
    final_kernel<<<1, 256>>>(values, out);
}

// round 4
// speedup vs baseline: 1.3365x; 1.3365x over previous
#include <cuda_runtime.h>
#include <math_constants.h>

#define D 1024
#define NKEYS 32768
#define TOPK 10
#define FT 512   // final kernel threads

// Scratch (allocation-free rule: __device__ globals)
__device__ float g_q[D];
__device__ float g_scores[NKEYS];
__device__ unsigned int g_max_enc;

// Order-preserving float->uint encoding (for atomicMax over signed floats)
__device__ __forceinline__ unsigned int fenc(float f) {
    unsigned int b = __float_as_uint(f);
    return (b & 0x80000000u) ? ~b : (b | 0x80000000u);
}
__device__ __forceinline__ float fdec(unsigned int u) {
    unsigned int b = (u & 0x80000000u) ? (u & 0x7FFFFFFFu) : ~u;
    return __uint_as_float(b);
}

// Kernel 1: q = Wq @ query + bq   (warp per output row, 8-deep batched loads)
__global__ __launch_bounds__(256, 2)
void proj_kernel(const float* __restrict__ query,
                 const float* __restrict__ Wq,
                 const float* __restrict__ bq) {
    __shared__ float4 sq[D / 4];
    int tid = threadIdx.x;
    sq[tid] = ((const float4*)query)[tid];   // 256 threads, 256 float4 — exact
    if (blockIdx.x == 0 && tid == 0) g_max_enc = 0u;  // reset for this launch
    __syncthreads();

    int warp = tid >> 5, lane = tid & 31;
    int row = blockIdx.x * 8 + warp;
    const float4* wrow = (const float4*)(Wq + (size_t)row * D);

    // Batch ALL loads first -> 8-deep MLP
    float4 w[8];
    #pragma unroll
    for (int i = 0; i < 8; i++) w[i] = wrow[lane + i * 32];

    float acc = 0.f;
    #pragma unroll
    for (int i = 0; i < 8; i++) {
        float4 q = sq[lane + i * 32];
        acc += w[i].x * q.x + w[i].y * q.y + w[i].z * q.z + w[i].w * q.w;
    }
    #pragma unroll
    for (int o = 16; o; o >>= 1) acc += __shfl_xor_sync(0xFFFFFFFFu, acc, o);
    if (lane == 0) g_q[row] = acc + bq[row];
}

// Kernel 2: scores[i] = keys[i] . q  (warp per row, 8-deep batched loads)
__global__ __launch_bounds__(256, 2)
void gemv_kernel(const float* __restrict__ keys) {
    __shared__ float4 sq[D / 4];
    __shared__ float srow[8];
    int tid = threadIdx.x;
    sq[tid] = ((const float4*)g_q)[tid];
    __syncthreads();

    int warp = tid >> 5, lane = tid & 31;
    int row = blockIdx.x * 8 + warp;
    const float4* kr = (const float4*)(keys + (size_t)row * D);

    // Batch ALL loads first -> 8-deep MLP (32 payload regs; launch_bounds
    // gives a 128-reg budget so ptxas keeps them all in flight)
    float4 w[8];
    #pragma unroll
    for (int i = 0; i < 8; i++) w[i] = kr[lane + i * 32];

    float acc = 0.f;
    #pragma unroll
    for (int i = 0; i < 8; i++) {
        float4 q = sq[lane + i * 32];
        acc += w[i].x * q.x + w[i].y * q.y + w[i].z * q.z + w[i].w * q.w;
    }
    #pragma unroll
    for (int o = 16; o; o >>= 1) acc += __shfl_xor_sync(0xFFFFFFFFu, acc, o);

    if (lane == 0) { g_scores[row] = acc; srow[warp] = acc; }
    __syncthreads();
    if (tid == 0) {
        float m = srow[0];
        #pragma unroll
        for (int i = 1; i < 8; i++) m = fmaxf(m, srow[i]);
        atomicMax(&g_max_enc, fenc(m));
    }
}

// Kernel 3 (single block, 512 threads): softmax denom + top-k + gather
__global__ __launch_bounds__(FT)
void final_kernel(const float* __restrict__ values,
                  float* __restrict__ out) {
    __shared__ float sv[FT * TOPK];
    __shared__ int   si[FT * TOPK];
    __shared__ float s_red[FT / 32];
    __shared__ float s_sum;

    int tid = threadIdx.x;
    const float inv = 0.03125f;  // 1/sqrt(1024)
    float mxs = fdec(g_max_enc) * inv;

    float lv[TOPK]; int li[TOPK];
    #pragma unroll
    for (int i = 0; i < TOPK; i++) { lv[i] = -CUDART_INF_F; li[i] = 0x7FFFFFFF; }

    // 4 independent accumulators break the MUFU dependency chain
    float s0 = 0.f, s1 = 0.f, s2 = 0.f, s3 = 0.f;
    for (int i = tid; i < NKEYS; i += 4 * FT) {
        float a = g_scores[i];
        float b = g_scores[i + FT];
        float c = g_scores[i + 2 * FT];
        float d = g_scores[i + 3 * FT];
        s0 += expf(a * inv - mxs);
        s1 += expf(b * inv - mxs);
        s2 += expf(c * inv - mxs);
        s3 += expf(d * inv - mxs);
        // top-k insertion (rarely taken)
        float cand[4] = {a, b, c, d};
        int   cidx[4] = {i, i + FT, i + 2 * FT, i + 3 * FT};
        #pragma unroll
        for (int t = 0; t < 4; t++) {
            float s = cand[t];
            if (s > lv[TOPK - 1]) {
                int j = TOPK - 1;
                while (j > 0 && s > lv[j - 1]) {
                    lv[j] = lv[j - 1]; li[j] = li[j - 1]; j--;
                }
                lv[j] = s; li[j] = cidx[t];
            }
        }
    }
    float sum = (s0 + s1) + (s2 + s3);

    #pragma unroll
    for (int o = 16; o; o >>= 1) sum += __shfl_xor_sync(0xFFFFFFFFu, sum, o);
    if ((tid & 31) == 0) s_red[tid >> 5] = sum;

    // publish local sorted lists
    #pragma unroll
    for (int i = 0; i < TOPK; i++) { sv[tid * TOPK + i] = lv[i]; si[tid * TOPK + i] = li[i]; }
    __syncthreads();

    if (tid == 0) {
        float t = 0.f;
        #pragma unroll
        for (int i = 0; i < FT / 32; i++) t += s_red[i];
        s_sum = t;
    }

    // tree-merge FT sorted 10-lists -> list at slot 0.
    // Inputs read from SHARED with dynamic index (LDS ok); outputs are
    // statically-indexed regs -> no local-memory spill.
    for (int step = FT / 2; step >= 1; step >>= 1) {
        float ov[TOPK]; int oi[TOPK];
        if (tid < step) {
            int ab = tid * TOPK, bb = (tid + step) * TOPK;
            int pa = 0, pb = 0;
            #pragma unroll
            for (int r = 0; r < TOPK; r++) {
                float avv = sv[ab + pa], bvv = sv[bb + pb];
                int   aii = si[ab + pa], bii = si[bb + pb];
                bool ta = (avv > bvv) || (avv == bvv && aii <= bii);
                if (ta) { ov[r] = avv; oi[r] = aii; pa++; }
                else    { ov[r] = bvv; oi[r] = bii; pb++; }
            }
        }
        __syncthreads();
        if (tid < step) {
            #pragma unroll
            for (int i = 0; i < TOPK; i++) { sv[tid * TOPK + i] = ov[i]; si[tid * TOPK + i] = oi[i]; }
        }
        __syncthreads();
    }

    // weights for top-k (descending order already)
    if (tid < TOPK) {
        out[TOPK * D + tid] = expf(sv[tid] * inv - mxs) / s_sum;
    }
    // fully parallel gather of the 10 value rows
    for (int e = tid; e < TOPK * D; e += FT) {
        int r = e >> 10;
        int c = e & (D - 1);
        out[e] = values[(size_t)si[r] * D + c];
    }
}

extern "C" void kernel_launch(void* const* d_in, const int* in_sizes, int n_in,
                              void* d_out, int out_size) {
    (void)in_sizes; (void)n_in; (void)out_size;
    const float* query  = (const float*)d_in[0];
    const float* keys   = (const float*)d_in[1];
    const float* values = (const float*)d_in[2];
    const float* Wq     = (const float*)d_in[3];
    const float* bq     = (const float*)d_in[4];
    float* out = (float*)d_out;

    proj_kernel<<<D / 8, 256>>>(query, Wq, bq);
    gemv_kernel<<<NKEYS / 8, 256>>>(keys);
    final_kernel<<<1, FT>>>(values, out);
}